// round 2
// baseline (speedup 1.0000x reference)
#include <cuda_runtime.h>

#define S  50000
#define E  20000
#define K  128
#define B  16384
#define NE 1000000

// ---------------- static device scratch (no allocation in kernel_launch) ----
__device__ float g_statA[S * K];
__device__ float g_statB[S * K];
__device__ float g_kdA[E * K];
__device__ float g_kdB[E * K];
// orderings: 0 = by rows_1 (u1, N=S), 1 = by rows_0 (u0, N=S),
//            2 = by cols_1 (i1, N=E), 3 = by cols_0 (i0, N=E)
__device__ int   g_rp[4][S + 1];    // counts -> exclusive rowptr
__device__ int   g_cur[4][S];       // scatter cursors
__device__ int   g_scol[4][NE];     // sorted source indices
__device__ float g_sval[4][NE];     // sorted edge values

__device__ __forceinline__ float sigm(float x) {
    return 1.0f / (1.0f + __expf(-x));
}

// ---------------- CSR build ------------------------------------------------
__global__ void k_zero() {
    int i = blockIdx.x * blockDim.x + threadIdx.x;
    if (i < 4 * (S + 1)) ((int*)g_rp)[i] = 0;
}

__global__ void k_hist(const int* __restrict__ r1, const int* __restrict__ r0,
                       const int* __restrict__ c1, const int* __restrict__ c0) {
    int e = blockIdx.x * blockDim.x + threadIdx.x;
    if (e >= NE) return;
    atomicAdd(&g_rp[0][r1[e]], 1);
    atomicAdd(&g_rp[1][r0[e]], 1);
    atomicAdd(&g_rp[2][c1[e]], 1);
    atomicAdd(&g_rp[3][c0[e]], 1);
}

// one block per ordering: exclusive scan of counts -> rowptr + cursor copy
__global__ void k_scan() {
    int o = blockIdx.x;
    int N = (o < 2) ? S : E;
    int* cnt = g_rp[o];
    int* cur = g_cur[o];
    __shared__ int wsum[32];
    __shared__ int srun;
    int tid = threadIdx.x;
    int lane = tid & 31, wid = tid >> 5;
    if (tid == 0) srun = 0;
    __syncthreads();
    int ntiles = (N + 1023) >> 10;
    for (int t = 0; t < ntiles; ++t) {
        int i = (t << 10) + tid;
        int v = (i < N) ? cnt[i] : 0;
        int incl = v;
        #pragma unroll
        for (int d = 1; d < 32; d <<= 1) {
            int n = __shfl_up_sync(0xffffffffu, incl, d);
            if (lane >= d) incl += n;
        }
        if (lane == 31) wsum[wid] = incl;
        __syncthreads();
        if (wid == 0) {
            int ws = wsum[lane];
            int wincl = ws;
            #pragma unroll
            for (int d = 1; d < 32; d <<= 1) {
                int n = __shfl_up_sync(0xffffffffu, wincl, d);
                if (lane >= d) wincl += n;
            }
            wsum[lane] = wincl - ws;  // exclusive warp offsets
        }
        __syncthreads();
        int run = srun;
        int excl = run + wsum[wid] + incl - v;
        if (i < N) { cnt[i] = excl; cur[i] = excl; }
        __syncthreads();  // everyone has read srun
        if (tid == 1023) srun = excl + v;  // tile-inclusive total
        __syncthreads();
    }
    if (tid == 0) cnt[N] = srun;
}

__global__ void k_scatter(const int* __restrict__ r1, const int* __restrict__ r0,
                          const int* __restrict__ c1, const int* __restrict__ c0,
                          const float* __restrict__ vui1, const float* __restrict__ vui0,
                          const float* __restrict__ viu1, const float* __restrict__ viu0) {
    int e = blockIdx.x * blockDim.x + threadIdx.x;
    if (e >= NE) return;
    int a = r1[e], b = r0[e], c = c1[e], d = c0[e];
    int p;
    p = atomicAdd(&g_cur[0][a], 1); g_scol[0][p] = c; g_sval[0][p] = vui1[e];
    p = atomicAdd(&g_cur[1][b], 1); g_scol[1][p] = d; g_sval[1][p] = vui0[e];
    p = atomicAdd(&g_cur[2][c], 1); g_scol[2][p] = a; g_sval[2][p] = viu1[e];
    p = atomicAdd(&g_cur[3][d], 1); g_scol[3][p] = b; g_sval[3][p] = viu0[e];
}

// ---------------- fused SpMM (one warp per destination row) ----------------
// is_stat=1: out_stat[s] = spmm(u1) + spmm(u0) + stat_in[s]*(d_i_1+d_i_0)   (gathers kdiff)
// is_stat=0: out_kd[e]   = spmm(i1) + spmm(i0) + kd_in[e]*(d_j_1+d_j_0)     (gathers stat)
__global__ void k_spmm(int obase, int nrows, int layer, int is_stat,
                       const float* __restrict__ semb, const float* __restrict__ eemb,
                       const float* __restrict__ dA, const float* __restrict__ dB) {
    const float* selfin;
    const float* gatherin;
    float* outp;
    if (is_stat) {
        selfin   = (layer == 0) ? semb : g_statA;
        gatherin = (layer == 0) ? eemb : g_kdA;
        outp     = (layer == 0) ? g_statA : g_statB;
    } else {
        selfin   = (layer == 0) ? eemb : g_kdA;
        gatherin = (layer == 0) ? semb : g_statA;
        outp     = (layer == 0) ? g_kdA : g_kdB;
    }
    int w    = (blockIdx.x * (int)blockDim.x + threadIdx.x) >> 5;
    int lane = threadIdx.x & 31;
    if (w >= nrows) return;

    const float4* X = (const float4*)gatherin;
    float4 sv = ((const float4*)selfin)[(size_t)w * 32 + lane];
    float d = dA[w] + dB[w];
    float ax = sv.x * d, ay = sv.y * d, az = sv.z * d, aw = sv.w * d;

    #pragma unroll
    for (int oo = 0; oo < 2; ++oo) {
        int o = obase + oo;
        const int*   sc  = g_scol[o];
        const float* svv = g_sval[o];
        int e = g_rp[o][w], end = g_rp[o][w + 1];
        for (; e + 4 <= end; e += 4) {
            int   c0 = sc[e + 0], c1 = sc[e + 1], c2 = sc[e + 2], c3 = sc[e + 3];
            float v0 = svv[e + 0], v1 = svv[e + 1], v2 = svv[e + 2], v3 = svv[e + 3];
            float4 x0 = X[(size_t)c0 * 32 + lane];
            float4 x1 = X[(size_t)c1 * 32 + lane];
            float4 x2 = X[(size_t)c2 * 32 + lane];
            float4 x3 = X[(size_t)c3 * 32 + lane];
            ax += v0 * x0.x; ay += v0 * x0.y; az += v0 * x0.z; aw += v0 * x0.w;
            ax += v1 * x1.x; ay += v1 * x1.y; az += v1 * x1.z; aw += v1 * x1.w;
            ax += v2 * x2.x; ay += v2 * x2.y; az += v2 * x2.z; aw += v2 * x2.w;
            ax += v3 * x3.x; ay += v3 * x3.y; az += v3 * x3.z; aw += v3 * x3.w;
        }
        for (; e < end; ++e) {
            int c = sc[e]; float v = svv[e];
            float4 x = X[(size_t)c * 32 + lane];
            ax += v * x.x; ay += v * x.y; az += v * x.z; aw += v * x.w;
        }
    }
    float4 r; r.x = ax; r.y = ay; r.z = az; r.w = aw;
    ((float4*)outp)[(size_t)w * 32 + lane] = r;
}

// ---------------- fused MLP head (16 queries per 256-thread block) ---------
__global__ void k_mlp(const int* __restrict__ stu_id, const int* __restrict__ exid,
                      const float* __restrict__ ikp,
                      const float* __restrict__ sbias, const float* __restrict__ edisc,
                      const float* __restrict__ W1, const float* __restrict__ b1,
                      const float* __restrict__ W2, const float* __restrict__ b2,
                      const float* __restrict__ W3, const float* __restrict__ b3,
                      float* __restrict__ outp) {
    __shared__ float xs[16 * 128];
    __shared__ float h1s[16 * 256];
    int tid = threadIdx.x;
    int qbase = blockIdx.x * 16;

    // phase A: x = ikp * (sigm(stat+bias) - sigm(kdiff)) * sigm(edisc)
    for (int idx = tid; idx < 16 * 128; idx += 256) {
        int r = idx >> 7, k = idx & 127;
        int q = qbase + r;
        int st = stu_id[q], ex = exid[q];
        float a  = sigm(g_statB[(size_t)st * 128 + k] + sbias[st]);
        float bk = sigm(g_kdB[(size_t)ex * 128 + k]);
        float ed = sigm(edisc[ex]);
        xs[idx] = ikp[(size_t)q * 128 + k] * (a - bk) * ed;
    }
    __syncthreads();

    // layer 1: 256 outputs, thread = output channel j, 16 rows in registers
    {
        float acc[16];
        #pragma unroll
        for (int r = 0; r < 16; ++r) acc[r] = 0.f;
        const float* wrow = W1 + (size_t)tid * 128;
        for (int k = 0; k < 128; ++k) {
            float w = fabsf(wrow[k]);
            #pragma unroll
            for (int r = 0; r < 16; ++r) acc[r] += w * xs[r * 128 + k];
        }
        float bb = b1[tid];
        #pragma unroll
        for (int r = 0; r < 16; ++r) h1s[r * 256 + tid] = tanhf(acc[r] + bb);
    }
    __syncthreads();

    // layer 2: 128 outputs, j = tid&127, 8 rows per thread; write h2 into xs
    {
        int j = tid & 127;
        int rb = (tid >> 7) * 8;
        float acc[8];
        #pragma unroll
        for (int r = 0; r < 8; ++r) acc[r] = 0.f;
        const float* wrow = W2 + (size_t)j * 256;
        for (int k = 0; k < 256; ++k) {
            float w = fabsf(wrow[k]);
            #pragma unroll
            for (int r = 0; r < 8; ++r) acc[r] += w * h1s[(rb + r) * 256 + k];
        }
        float bb = b2[j];
        #pragma unroll
        for (int r = 0; r < 8; ++r) xs[(rb + r) * 128 + j] = tanhf(acc[r] + bb);
    }
    __syncthreads();

    // layer 3: warp per 2 rows, butterfly reduce
    {
        int wid = tid >> 5, lane = tid & 31;
        #pragma unroll
        for (int rr = 0; rr < 2; ++rr) {
            int r = wid * 2 + rr;
            float s = 0.f;
            #pragma unroll
            for (int k = lane; k < 128; k += 32) s += fabsf(W3[k]) * xs[r * 128 + k];
            #pragma unroll
            for (int d = 16; d; d >>= 1) s += __shfl_xor_sync(0xffffffffu, s, d);
            if (lane == 0) outp[qbase + r] = sigm(s + b3[0]);
        }
    }
}

// ---------------- launch ----------------------------------------------------
extern "C" void kernel_launch(void* const* d_in, const int* in_sizes, int n_in,
                              void* d_out, int out_size) {
    const int*   stu_id = (const int*)d_in[0];
    const int*   exid   = (const int*)d_in[1];
    const float* ikp    = (const float*)d_in[2];
    const int*   rows1  = (const int*)d_in[3];
    const int*   cols1  = (const int*)d_in[4];
    const int*   rows0  = (const int*)d_in[5];
    const int*   cols0  = (const int*)d_in[6];
    const float* vui1   = (const float*)d_in[7];
    const float* viu1   = (const float*)d_in[8];
    const float* vui0   = (const float*)d_in[9];
    const float* viu0   = (const float*)d_in[10];
    const float* di1    = (const float*)d_in[11];
    const float* dj1    = (const float*)d_in[12];
    const float* di0    = (const float*)d_in[13];
    const float* dj0    = (const float*)d_in[14];
    const float* semb   = (const float*)d_in[15];
    const float* eemb   = (const float*)d_in[16];
    const float* sbias  = (const float*)d_in[17];
    const float* edisc  = (const float*)d_in[18];
    const float* W1     = (const float*)d_in[19];
    const float* b1     = (const float*)d_in[20];
    const float* W2     = (const float*)d_in[21];
    const float* b2     = (const float*)d_in[22];
    const float* W3     = (const float*)d_in[23];
    const float* b3     = (const float*)d_in[24];
    float* outp = (float*)d_out;

    // CSR build (per launch; deterministic counts, cursor order only perturbs fp lsb)
    k_zero<<<(4 * (S + 1) + 255) / 256, 256>>>();
    k_hist<<<(NE + 255) / 256, 256>>>(rows1, rows0, cols1, cols0);
    k_scan<<<4, 1024>>>();
    k_scatter<<<(NE + 255) / 256, 256>>>(rows1, rows0, cols1, cols0,
                                         vui1, vui0, viu1, viu0);

    // layer 1
    k_spmm<<<(S * 32 + 255) / 256, 256>>>(0, S, 0, 1, semb, eemb, di1, di0);
    k_spmm<<<(E * 32 + 255) / 256, 256>>>(2, E, 0, 0, semb, eemb, dj1, dj0);
    // layer 2
    k_spmm<<<(S * 32 + 255) / 256, 256>>>(0, S, 1, 1, semb, eemb, di1, di0);
    k_spmm<<<(E * 32 + 255) / 256, 256>>>(2, E, 1, 0, semb, eemb, dj1, dj0);

    // prediction head
    k_mlp<<<B / 16, 256>>>(stu_id, exid, ikp, sbias, edisc,
                           W1, b1, W2, b2, W3, b3, outp);
}

// round 3
// speedup vs baseline: 1.0974x; 1.0974x over previous
#include <cuda_runtime.h>
#include <cuda_fp16.h>

#define S  50000
#define E  20000
#define K  128
#define B  16384
#define NE 1000000

// ---------------- static device scratch ------------------------------------
__device__ float  g_statA[S * K];
__device__ float  g_statB[S * K];
__device__ float  g_kdA[E * K];
__device__ float  g_kdB[E * K];
__device__ __half g_sembH[S * K];
__device__ __half g_eembH[E * K];
__device__ __half g_statAH[S * K];
__device__ __half g_kdAH[E * K];
// orderings: 0 = by rows_1 (u1, N=S), 1 = by rows_0 (u0, N=S),
//            2 = by cols_1 (i1, N=E), 3 = by cols_0 (i0, N=E)
__device__ int    g_rp[4][S + 1];      // counts -> exclusive rowptr
__device__ int    g_cur[4][S];         // scatter cursors
__device__ int2   g_edge[4][NE];       // packed (src_col, val_bits), sorted by dest
__device__ unsigned char g_needS[S];
__device__ unsigned char g_needE[E];
__device__ int    g_list[2 * B];       // layer-2 work list (row | kd_flag<<30)
__device__ int    g_cnt;

__device__ __forceinline__ float sigm(float x) {
    return 1.0f / (1.0f + __expf(-x));
}

// ---------------- setup: zero + flags + fp16 conversion --------------------
__global__ void k_zero() {
    int i = blockIdx.x * blockDim.x + threadIdx.x;
    if (i < 4 * (S + 1)) ((int*)g_rp)[i] = 0;
    if (i < S) g_needS[i] = 0;
    if (i < E) g_needE[i] = 0;
    if (i == 0) g_cnt = 0;
}

__global__ void k_flags(const int* __restrict__ stu_id, const int* __restrict__ exid) {
    int q = blockIdx.x * blockDim.x + threadIdx.x;
    if (q >= B) return;
    g_needS[stu_id[q]] = 1;   // benign races
    g_needE[exid[q]]   = 1;
}

__global__ void k_compact() {
    int i = blockIdx.x * blockDim.x + threadIdx.x;
    if (i < S) {
        if (g_needS[i]) { int p = atomicAdd(&g_cnt, 1); g_list[p] = i; }
    } else if (i < S + E) {
        int j = i - S;
        if (g_needE[j]) { int p = atomicAdd(&g_cnt, 1); g_list[p] = j | (1 << 30); }
    }
}

__global__ void k_conv(const float* __restrict__ semb, const float* __restrict__ eemb) {
    int i = blockIdx.x * blockDim.x + threadIdx.x;
    const int nS = S * K / 2, nE = E * K / 2;
    if (i < nS) {
        float2 f = ((const float2*)semb)[i];
        ((__half2*)g_sembH)[i] = __floats2half2_rn(f.x, f.y);
    } else if (i < nS + nE) {
        int j = i - nS;
        float2 f = ((const float2*)eemb)[j];
        ((__half2*)g_eembH)[j] = __floats2half2_rn(f.x, f.y);
    }
}

// ---------------- CSR build ------------------------------------------------
__global__ void k_hist(const int* __restrict__ r1, const int* __restrict__ r0,
                       const int* __restrict__ c1, const int* __restrict__ c0) {
    int e = blockIdx.x * blockDim.x + threadIdx.x;
    if (e >= NE) return;
    atomicAdd(&g_rp[0][r1[e]], 1);
    atomicAdd(&g_rp[1][r0[e]], 1);
    atomicAdd(&g_rp[2][c1[e]], 1);
    atomicAdd(&g_rp[3][c0[e]], 1);
}

// one block per ordering: exclusive scan of counts -> rowptr + cursor copy
__global__ void k_scan() {
    int o = blockIdx.x;
    int N = (o < 2) ? S : E;
    int* cnt = g_rp[o];
    int* cur = g_cur[o];
    __shared__ int wsum[32];
    __shared__ int srun;
    int tid = threadIdx.x;
    int lane = tid & 31, wid = tid >> 5;
    if (tid == 0) srun = 0;
    __syncthreads();
    int ntiles = (N + 1023) >> 10;
    for (int t = 0; t < ntiles; ++t) {
        int i = (t << 10) + tid;
        int v = (i < N) ? cnt[i] : 0;
        int incl = v;
        #pragma unroll
        for (int d = 1; d < 32; d <<= 1) {
            int n = __shfl_up_sync(0xffffffffu, incl, d);
            if (lane >= d) incl += n;
        }
        if (lane == 31) wsum[wid] = incl;
        __syncthreads();
        if (wid == 0) {
            int ws = wsum[lane];
            int wincl = ws;
            #pragma unroll
            for (int d = 1; d < 32; d <<= 1) {
                int n = __shfl_up_sync(0xffffffffu, wincl, d);
                if (lane >= d) wincl += n;
            }
            wsum[lane] = wincl - ws;
        }
        __syncthreads();
        int run = srun;
        int excl = run + wsum[wid] + incl - v;
        if (i < N) { cnt[i] = excl; cur[i] = excl; }
        __syncthreads();
        if (tid == 1023) srun = excl + v;
        __syncthreads();
    }
    if (tid == 0) cnt[N] = srun;
}

__global__ void k_scatter(const int* __restrict__ r1, const int* __restrict__ r0,
                          const int* __restrict__ c1, const int* __restrict__ c0,
                          const float* __restrict__ vui1, const float* __restrict__ vui0,
                          const float* __restrict__ viu1, const float* __restrict__ viu0) {
    int e = blockIdx.x * blockDim.x + threadIdx.x;
    if (e >= NE) return;
    int a = r1[e], b = r0[e], c = c1[e], d = c0[e];
    int p;
    p = atomicAdd(&g_cur[0][a], 1); g_edge[0][p] = make_int2(c, __float_as_int(vui1[e]));
    p = atomicAdd(&g_cur[1][b], 1); g_edge[1][p] = make_int2(d, __float_as_int(vui0[e]));
    p = atomicAdd(&g_cur[2][c], 1); g_edge[2][p] = make_int2(a, __float_as_int(viu1[e]));
    p = atomicAdd(&g_cur[3][d], 1); g_edge[3][p] = make_int2(b, __float_as_int(viu0[e]));
}

// ---------------- SpMM core (warp per dest row, fp16 gathers) --------------
__device__ __forceinline__ void acc_h(uint2 r, float v,
                                      float& ax, float& ay, float& az, float& aw) {
    __half2 h0 = *reinterpret_cast<__half2*>(&r.x);
    __half2 h1 = *reinterpret_cast<__half2*>(&r.y);
    float2 f0 = __half22float2(h0);
    float2 f1 = __half22float2(h1);
    ax += v * f0.x; ay += v * f0.y; az += v * f1.x; aw += v * f1.y;
}

__device__ __forceinline__ void gather_ord(int o, int row, int lane,
                                           const uint2* __restrict__ XH,
                                           float& ax, float& ay, float& az, float& aw) {
    const int2* __restrict__ ed = g_edge[o];
    int e = g_rp[o][row], end = g_rp[o][row + 1];
    for (; e + 4 <= end; e += 4) {
        int2 m0 = ed[e + 0], m1 = ed[e + 1], m2 = ed[e + 2], m3 = ed[e + 3];
        uint2 r0 = XH[(size_t)m0.x * 32 + lane];
        uint2 r1 = XH[(size_t)m1.x * 32 + lane];
        uint2 r2 = XH[(size_t)m2.x * 32 + lane];
        uint2 r3 = XH[(size_t)m3.x * 32 + lane];
        acc_h(r0, __int_as_float(m0.y), ax, ay, az, aw);
        acc_h(r1, __int_as_float(m1.y), ax, ay, az, aw);
        acc_h(r2, __int_as_float(m2.y), ax, ay, az, aw);
        acc_h(r3, __int_as_float(m3.y), ax, ay, az, aw);
    }
    for (; e < end; ++e) {
        int2 m = ed[e];
        uint2 r = XH[(size_t)m.x * 32 + lane];
        acc_h(r, __int_as_float(m.y), ax, ay, az, aw);
    }
}

// layer 1: full S+E rows, writes fp32 result + fp16 gather copy
__global__ void k_spmm1(const float* __restrict__ semb, const float* __restrict__ eemb,
                        const float* __restrict__ di1, const float* __restrict__ di0,
                        const float* __restrict__ dj1, const float* __restrict__ dj0) {
    int w = (blockIdx.x * (int)blockDim.x + threadIdx.x) >> 5;
    int lane = threadIdx.x & 31;
    if (w >= S + E) return;
    int o0, row;
    const uint2*  XH;
    const float*  selfin;
    float d;
    float*  outF;
    __half* outH;
    if (w < S) {
        row = w; o0 = 0; XH = (const uint2*)g_eembH; selfin = semb;
        d = di1[row] + di0[row]; outF = g_statA; outH = g_statAH;
    } else {
        row = w - S; o0 = 2; XH = (const uint2*)g_sembH; selfin = eemb;
        d = dj1[row] + dj0[row]; outF = g_kdA; outH = g_kdAH;
    }
    float4 sv = ((const float4*)selfin)[(size_t)row * 32 + lane];
    float ax = sv.x * d, ay = sv.y * d, az = sv.z * d, aw = sv.w * d;
    gather_ord(o0 + 0, row, lane, XH, ax, ay, az, aw);
    gather_ord(o0 + 1, row, lane, XH, ax, ay, az, aw);
    float4 r; r.x = ax; r.y = ay; r.z = az; r.w = aw;
    ((float4*)outF)[(size_t)row * 32 + lane] = r;
    __half2 h0 = __floats2half2_rn(ax, ay);
    __half2 h1 = __floats2half2_rn(az, aw);
    uint2 hw; hw.x = *(unsigned int*)&h0; hw.y = *(unsigned int*)&h1;
    ((uint2*)outH)[(size_t)row * 32 + lane] = hw;
}

// layer 2: only rows needed by the MLP (work list), fp32 output only
__global__ void k_spmm2(const float* __restrict__ di1, const float* __restrict__ di0,
                        const float* __restrict__ dj1, const float* __restrict__ dj0) {
    int idx = (blockIdx.x * (int)blockDim.x + threadIdx.x) >> 5;
    int lane = threadIdx.x & 31;
    if (idx >= g_cnt) return;
    int enc = g_list[idx];
    int row = enc & 0x3FFFFFFF;
    int o0;
    const uint2* XH;
    const float* selfin;
    float d;
    float* outF;
    if (enc & (1 << 30)) {   // kdiff row: gathers layer-1 stat
        o0 = 2; XH = (const uint2*)g_statAH; selfin = g_kdA;
        d = dj1[row] + dj0[row]; outF = g_kdB;
    } else {                 // stat row: gathers layer-1 kdiff
        o0 = 0; XH = (const uint2*)g_kdAH; selfin = g_statA;
        d = di1[row] + di0[row]; outF = g_statB;
    }
    float4 sv = ((const float4*)selfin)[(size_t)row * 32 + lane];
    float ax = sv.x * d, ay = sv.y * d, az = sv.z * d, aw = sv.w * d;
    gather_ord(o0 + 0, row, lane, XH, ax, ay, az, aw);
    gather_ord(o0 + 1, row, lane, XH, ax, ay, az, aw);
    float4 r; r.x = ax; r.y = ay; r.z = az; r.w = aw;
    ((float4*)outF)[(size_t)row * 32 + lane] = r;
}

// ---------------- fused MLP head (16 queries per 256-thread block) ---------
__global__ void k_mlp(const int* __restrict__ stu_id, const int* __restrict__ exid,
                      const float* __restrict__ ikp,
                      const float* __restrict__ sbias, const float* __restrict__ edisc,
                      const float* __restrict__ W1, const float* __restrict__ b1,
                      const float* __restrict__ W2, const float* __restrict__ b2,
                      const float* __restrict__ W3, const float* __restrict__ b3,
                      float* __restrict__ outp) {
    __shared__ float xs[16 * 128];
    __shared__ float h1s[16 * 256];
    int tid = threadIdx.x;
    int qbase = blockIdx.x * 16;

    for (int idx = tid; idx < 16 * 128; idx += 256) {
        int r = idx >> 7, k = idx & 127;
        int q = qbase + r;
        int st = stu_id[q], ex = exid[q];
        float a  = sigm(g_statB[(size_t)st * 128 + k] + sbias[st]);
        float bk = sigm(g_kdB[(size_t)ex * 128 + k]);
        float ed = sigm(edisc[ex]);
        xs[idx] = ikp[(size_t)q * 128 + k] * (a - bk) * ed;
    }
    __syncthreads();

    {
        float acc[16];
        #pragma unroll
        for (int r = 0; r < 16; ++r) acc[r] = 0.f;
        const float* wrow = W1 + (size_t)tid * 128;
        for (int k = 0; k < 128; ++k) {
            float w = fabsf(wrow[k]);
            #pragma unroll
            for (int r = 0; r < 16; ++r) acc[r] += w * xs[r * 128 + k];
        }
        float bb = b1[tid];
        #pragma unroll
        for (int r = 0; r < 16; ++r) h1s[r * 256 + tid] = tanhf(acc[r] + bb);
    }
    __syncthreads();

    {
        int j = tid & 127;
        int rb = (tid >> 7) * 8;
        float acc[8];
        #pragma unroll
        for (int r = 0; r < 8; ++r) acc[r] = 0.f;
        const float* wrow = W2 + (size_t)j * 256;
        for (int k = 0; k < 256; ++k) {
            float w = fabsf(wrow[k]);
            #pragma unroll
            for (int r = 0; r < 8; ++r) acc[r] += w * h1s[(rb + r) * 256 + k];
        }
        float bb = b2[j];
        #pragma unroll
        for (int r = 0; r < 8; ++r) xs[(rb + r) * 128 + j] = tanhf(acc[r] + bb);
    }
    __syncthreads();

    {
        int wid = tid >> 5, lane = tid & 31;
        #pragma unroll
        for (int rr = 0; rr < 2; ++rr) {
            int r = wid * 2 + rr;
            float s = 0.f;
            #pragma unroll
            for (int k = lane; k < 128; k += 32) s += fabsf(W3[k]) * xs[r * 128 + k];
            #pragma unroll
            for (int d = 16; d; d >>= 1) s += __shfl_xor_sync(0xffffffffu, s, d);
            if (lane == 0) outp[qbase + r] = sigm(s + b3[0]);
        }
    }
}

// ---------------- launch ----------------------------------------------------
extern "C" void kernel_launch(void* const* d_in, const int* in_sizes, int n_in,
                              void* d_out, int out_size) {
    const int*   stu_id = (const int*)d_in[0];
    const int*   exid   = (const int*)d_in[1];
    const float* ikp    = (const float*)d_in[2];
    const int*   rows1  = (const int*)d_in[3];
    const int*   cols1  = (const int*)d_in[4];
    const int*   rows0  = (const int*)d_in[5];
    const int*   cols0  = (const int*)d_in[6];
    const float* vui1   = (const float*)d_in[7];
    const float* viu1   = (const float*)d_in[8];
    const float* vui0   = (const float*)d_in[9];
    const float* viu0   = (const float*)d_in[10];
    const float* di1    = (const float*)d_in[11];
    const float* dj1    = (const float*)d_in[12];
    const float* di0    = (const float*)d_in[13];
    const float* dj0    = (const float*)d_in[14];
    const float* semb   = (const float*)d_in[15];
    const float* eemb   = (const float*)d_in[16];
    const float* sbias  = (const float*)d_in[17];
    const float* edisc  = (const float*)d_in[18];
    const float* W1     = (const float*)d_in[19];
    const float* b1     = (const float*)d_in[20];
    const float* W2     = (const float*)d_in[21];
    const float* b2     = (const float*)d_in[22];
    const float* W3     = (const float*)d_in[23];
    const float* b3     = (const float*)d_in[24];
    float* outp = (float*)d_out;

    k_zero<<<(4 * (S + 1) + 255) / 256, 256>>>();
    k_flags<<<(B + 255) / 256, 256>>>(stu_id, exid);
    k_compact<<<(S + E + 255) / 256, 256>>>();
    k_conv<<<((S + E) * K / 2 + 255) / 256, 256>>>(semb, eemb);
    k_hist<<<(NE + 255) / 256, 256>>>(rows1, rows0, cols1, cols0);
    k_scan<<<4, 1024>>>();
    k_scatter<<<(NE + 255) / 256, 256>>>(rows1, rows0, cols1, cols0,
                                         vui1, vui0, viu1, viu0);

    // layer 1 (full) + layer 2 (dest-filtered)
    k_spmm1<<<((S + E) * 32 + 255) / 256, 256>>>(semb, eemb, di1, di0, dj1, dj0);
    k_spmm2<<<(2 * B * 32 + 255) / 256, 256>>>(di1, di0, dj1, dj0);

    k_mlp<<<B / 16, 256>>>(stu_id, exid, ikp, sbias, edisc,
                           W1, b1, W2, b2, W3, b3, outp);
}